// round 15
// baseline (speedup 1.0000x reference)
#include <cuda_runtime.h>
#include <cstdint>

// ---------------------------------------------------------------------------
// NodeMLP: x[N,32] -> Linear(32,128) -> graphBN(G=16) -> LeakyReLU(0.01)
//          -> Linear(128,64) -> graphBN -> LeakyReLU -> segment_max into M
//
// R13: PERSISTENT k_fused (296 CTAs): weights staged once per CTA, 64-row
//      tiles streamed with double-buffered cp.async. 2 barriers/tile,
//      direct global stats atomics. xtx/pool/CSR machinery unchanged.
// ---------------------------------------------------------------------------

constexpr int D0 = 32, D1 = 128, D2 = 64, GG = 16;
constexpr float EPS = 1e-5f;
constexpr float SLOPE = 0.01f;

constexpr size_t N_MAX = 1048576;
constexpr size_t M_MAX = 65536;

// layer-2 stats accumulators: [0,1024) sum, [1024,2048) sumsq  ([g][64])
constexpr int OFF_S2 = 0, OFF_SS2 = 1024, ACC_TOT = 2048;

__device__ float g_h2[N_MAX * (size_t)D2];   // raw h2, rows in CSR-permuted order
__device__ float g_acc[ACC_TOT];
__device__ float g_S[GG * 1024];             // per-graph x^T x (32x32)
__device__ float g_m[GG * 32];               // per-graph sum x
__device__ float g_scale1[GG * D1], g_shift1[GG * D1];
__device__ float g_scale2[GG * D2], g_shift2[GG * D2];
__device__ int   g_ni[N_MAX], g_si[N_MAX];
__device__ int   g_pos[N_MAX];               // node -> CSR slot
__device__ int   g_nip[N_MAX];               // CSR slot -> graph id
__device__ int   g_segcnt[M_MAX], g_segoff[M_MAX + 1], g_cursor[M_MAX];
__device__ int   g_goff[GG + 1];
__device__ int   g_is64;

// ---------------------------------------------------------------------------
__device__ __forceinline__ uint32_t f2tf(float f) {
    uint32_t u;
    asm("cvt.rna.tf32.f32 %0, %1;" : "=r"(u) : "f"(f));
    return u;
}

// D += A(16x8,row) * B(8x8,col)   tf32 in, fp32 accum
__device__ __forceinline__ void mma_tf32(float* d, const uint32_t* a, const uint32_t* b) {
    asm volatile(
        "mma.sync.aligned.m16n8k8.row.col.f32.tf32.tf32.f32 "
        "{%0,%1,%2,%3}, {%4,%5,%6,%7}, {%8,%9}, {%0,%1,%2,%3};"
        : "+f"(d[0]), "+f"(d[1]), "+f"(d[2]), "+f"(d[3])
        : "r"(a[0]), "r"(a[1]), "r"(a[2]), "r"(a[3]), "r"(b[0]), "r"(b[1]));
}

// permuted position of k within its 8-group: (k,k+4) become adjacent
__device__ __forceinline__ int kperm(int k) {
    return (k & ~7) | ((k & 3) << 1) | ((k >> 2) & 1);
}

// first index i in sorted g_ni[0..n) with g_ni[i] >= v
__device__ __forceinline__ int lbound(int n, int v) {
    int lo = 0, hi = n;
    while (lo < hi) {
        int mid = (lo + hi) >> 1;
        if (g_ni[mid] < v) lo = mid + 1; else hi = mid;
    }
    return lo;
}

// ---------------------------------------------------------------------------
// zero + detect (int64 vs int32 index width) merged
__global__ void k_zero(const void* sidx, int M) {
    int i = blockIdx.x * blockDim.x + threadIdx.x;
    if (i == 0) {
        const long long* p = (const long long*)sidx;
        int ok64 = 1;
        for (int t = 0; t < 256; t++) {
            unsigned long long v = (unsigned long long)p[t];
            if (v >= (unsigned long long)M) { ok64 = 0; break; }
        }
        g_is64 = ok64;
    }
    if (i < ACC_TOT) g_acc[i] = 0.f;
    if (i < GG * 1024) g_S[i] = 0.f;
    if (i < GG * 32) g_m[i] = 0.f;
    if (i < M) { g_segcnt[i] = 0; g_cursor[i] = 0; }
}

// convert indices to int32 + histogram super_index in one pass
__global__ void k_cvthist(const void* nidx, const void* sidx, int N) {
    int i = blockIdx.x * blockDim.x + threadIdx.x;
    if (i >= N) return;
    int ni, si;
    if (g_is64) {
        ni = (int)((const long long*)nidx)[i];
        si = (int)((const long long*)sidx)[i];
    } else {
        ni = ((const int*)nidx)[i];
        si = ((const int*)sidx)[i];
    }
    g_ni[i] = ni;
    g_si[i] = si;
    atomicAdd(&g_segcnt[si], 1);
}

// per-graph row ranges (norm_index is sorted)
__global__ void k_goff(int N) {
    int t = threadIdx.x;
    if (t <= GG) g_goff[t] = lbound(N, t);
}

// ---------------------------------------------------------------------------
// Per-graph moments via tf32 MMA with a 4-stage cp.async pipeline.
// A channel of constant 1.0 is appended (col 32) so S[i][32] = m[i].
constexpr int XTX_ROWS   = 2048;
constexpr int XTX_STAGES = 4;
constexpr int XTX_STG_B  = 128 * 40 * 4;
constexpr int XTX_SMEM   = XTX_STAGES * XTX_STG_B + 32 * 33 * 4;

__global__ __launch_bounds__(256) void k_xtx(const float* __restrict__ x, int N) {
    extern __shared__ unsigned char xsm[];
    uint32_t (*sX)[128][40] = (uint32_t(*)[128][40])xsm;
    float* sS = (float*)(xsm + XTX_STAGES * XTX_STG_B);   // [32][33]

    const int g = blockIdx.y;
    const int lo = g_goff[g], hi = g_goff[g + 1];
    const long long base = (long long)lo + (long long)blockIdx.x * XTX_ROWS;
    if (base >= hi) return;
    const int rows = min(XTX_ROWS, (int)(hi - base));
    const int nchunks = (rows + 127) >> 7;

    const int tid = threadIdx.x, lane = tid & 31, wid = tid >> 5;

    for (int i = tid; i < 32 * 33; i += 256) sS[i] = 0.f;
    for (int i = tid; i < XTX_STAGES * 128; i += 256) {
        int s = i >> 7, r = i & 127;
        sX[s][r][32] = 0x3f800000u;
#pragma unroll
        for (int c = 33; c < 40; c++) sX[s][r][c] = 0u;
    }
    __syncthreads();

    const int lrow = tid >> 1, lcol = (tid & 1) * 16;

#define XTX_ISSUE(CH) do {                                                    \
        int _r = (CH) * 128 + lrow;                                           \
        int _sz = (_r < rows) ? 16 : 0;                                       \
        const float* _src = x + (size_t)(base + min(_r, rows - 1)) * D0 + lcol; \
        uint32_t _dst = (uint32_t)__cvta_generic_to_shared(&sX[(CH) & 3][lrow][lcol]); \
        _Pragma("unroll")                                                     \
        for (int _i = 0; _i < 4; _i++)                                        \
            asm volatile("cp.async.ca.shared.global [%0], [%1], 16, %2;"      \
                         :: "r"(_dst + 16 * _i), "l"(_src + 4 * _i), "r"(_sz) \
                         : "memory");                                         \
    } while (0)

    for (int ch = 0; ch < 3; ch++) {
        if (ch < nchunks) XTX_ISSUE(ch);
        asm volatile("cp.async.commit_group;" ::: "memory");
    }

    float acc[2][5][4];
#pragma unroll
    for (int m = 0; m < 2; m++)
#pragma unroll
        for (int jf = 0; jf < 5; jf++)
#pragma unroll
            for (int q = 0; q < 4; q++) acc[m][jf][q] = 0.f;

    for (int ch = 0; ch < nchunks; ch++) {
        asm volatile("cp.async.wait_group 2;" ::: "memory");
        __syncthreads();
        if (ch + 3 < nchunks) XTX_ISSUE(ch + 3);
        asm volatile("cp.async.commit_group;" ::: "memory");

        const uint32_t (*cur)[40] = sX[ch & 3];
#pragma unroll
        for (int half = 0; half < 2; half++) {
            const int k0 = half * 64 + wid * 8 + (lane & 3);
            uint32_t a[2][4];
#pragma unroll
            for (int m = 0; m < 2; m++) {
                int i0 = (lane >> 2) + 16 * m;
                a[m][0] = cur[k0][i0];     a[m][1] = cur[k0][i0 + 8];
                a[m][2] = cur[k0 + 4][i0]; a[m][3] = cur[k0 + 4][i0 + 8];
            }
#pragma unroll
            for (int jf = 0; jf < 5; jf++) {
                int j0 = jf * 8 + (lane >> 2);
                uint32_t b[2] = { cur[k0][j0], cur[k0 + 4][j0] };
#pragma unroll
                for (int m = 0; m < 2; m++) mma_tf32(acc[m][jf], a[m], b);
            }
        }
    }
#undef XTX_ISSUE

#pragma unroll
    for (int m = 0; m < 2; m++)
#pragma unroll
        for (int jf = 0; jf < 5; jf++)
#pragma unroll
            for (int q = 0; q < 4; q++) {
                int i = (lane >> 2) + 16 * m + 8 * (q >> 1);
                int j = jf * 8 + 2 * (lane & 3) + (q & 1);
                if (j <= 32) atomicAdd(&sS[i * 33 + j], acc[m][jf][q]);
            }
    __syncthreads();

    for (int e = tid; e < 32 * 33; e += 256) {
        int i = e / 33, j = e % 33;
        if (j < 32) atomicAdd(&g_S[g * 1024 + i * 32 + j], sS[e]);
        else        atomicAdd(&g_m[g * 32 + i], sS[e]);
    }
}

// ---------------------------------------------------------------------------
// layer-1 scale/shift from analytic moments. grid = GG blocks x 128 threads.
__global__ void k_fin1(const float* __restrict__ W1, const float* __restrict__ b1,
                       const float* __restrict__ gamma, const float* __restrict__ beta,
                       int N)
{
    __shared__ float sS[1024];
    __shared__ float sM[32];
    const int g = blockIdx.x, c = threadIdx.x;
    for (int i = c; i < 1024; i += 128) sS[i] = g_S[g * 1024 + i];
    if (c < 32) sM[c] = g_m[g * 32 + c];
    __syncthreads();

    float w[32];
#pragma unroll
    for (int k = 0; k < 32; k++) w[k] = W1[c * 32 + k];

    float dot = 0.f, quad = 0.f;
#pragma unroll 4
    for (int k = 0; k < 32; k++) {
        float t = 0.f;
#pragma unroll
        for (int l = 0; l < 32; l++) t += sS[k * 32 + l] * w[l];
        quad += w[k] * t;
        dot += w[k] * sM[k];
    }
    float cnt = (float)(g_goff[g + 1] - g_goff[g]);
    float bias = b1[c];
    float sum_h = dot + cnt * bias;
    float sumsq = quad + 2.f * bias * dot + cnt * bias * bias;
    float cc = fmaxf(cnt, 1.f);
    float mean = sum_h / cc;
    float var = fmaxf(sumsq / cc - mean * mean, 0.f);
    float s = gamma[c] * rsqrtf(var + EPS);
    g_scale1[g * D1 + c] = s;
    g_shift1[g * D1 + c] = beta[c] - mean * s;
}

// layer-2 scale/shift. grid = GG x 64.
__global__ void k_fin2(const float* __restrict__ gamma, const float* __restrict__ beta, int N) {
    const int g = blockIdx.x, c = threadIdx.x;
    float cc = fmaxf((float)(g_goff[g + 1] - g_goff[g]), 1.f);
    float mean = g_acc[OFF_S2 + g * D2 + c] / cc;
    float var = fmaxf(g_acc[OFF_SS2 + g * D2 + c] / cc - mean * mean, 0.f);
    float s = gamma[c] * rsqrtf(var + EPS);
    g_scale2[g * D2 + c] = s;
    g_shift2[g * D2 + c] = beta[c] - mean * s;
}

// fast two-level scan, single block of 1024 threads
__global__ void k_scan(int M) {
    __shared__ int wsum[32];
    int tid = threadIdx.x, lane = tid & 31, w = tid >> 5;
    int per = (M + 1023) >> 10;
    int s = tid * per;
    int e = min(s + per, M);
    int sum = 0;
    for (int i = s; i < e; i++) sum += g_segcnt[i];
    int v = sum;
#pragma unroll
    for (int off = 1; off < 32; off <<= 1) {
        int t = __shfl_up_sync(0xffffffffu, v, off);
        if (lane >= off) v += t;
    }
    if (lane == 31) wsum[w] = v;
    __syncthreads();
    if (w == 0) {
        int t = wsum[lane];
#pragma unroll
        for (int off = 1; off < 32; off <<= 1) {
            int u = __shfl_up_sync(0xffffffffu, t, off);
            if (lane >= off) t += u;
        }
        wsum[lane] = t;
    }
    __syncthreads();
    int run = (w ? wsum[w - 1] : 0) + (v - sum);
    for (int i = s; i < e; i++) { g_segoff[i] = run; run += g_segcnt[i]; }
    if (e == M) g_segoff[M] = run;
}

// CSR slot assignment: node i -> pos; also slot -> graph id for the pool
__global__ void k_fill(int N) {
    int i = blockIdx.x * blockDim.x + threadIdx.x;
    if (i >= N) return;
    int s = g_si[i];
    int pos = g_segoff[s] + atomicAdd(&g_cursor[s], 1);
    g_pos[i] = pos;
    g_nip[pos] = g_ni[i];
}

// ---------------------------------------------------------------------------
// PERSISTENT fused kernel. Grid = 2*148 CTAs x 256 threads, 2 CTAs/SM.
// Weights staged once; 64-row tiles streamed with 2-stage cp.async.
//
// smem (bytes):
//   [0,      18432)  sX[2][64][36]  raw fp32 x (cp.async; fed as tf32 bits)
//   [18432,  38912)  sW1[128][40]   perm tf32
//   [38912,  73728)  sW2[64][136]   perm tf32
//   [73728, 108544)  sH [64][136]   perm tf32 normalized h1
constexpr int FS_SX  = 0;
constexpr int FS_W1  = 18432;
constexpr int FS_W2  = 38912;
constexpr int FS_H   = 73728;
constexpr int FUSED_SMEM = 108544;
constexpr int FROWS = 64;

__global__ __launch_bounds__(256, 2) void k_fused(
    const float* __restrict__ x, const float* __restrict__ W1,
    const float* __restrict__ b1, const float* __restrict__ W2,
    const float* __restrict__ b2, int N, int nblk)
{
    extern __shared__ unsigned char dsm[];
    uint32_t (*sX)[64][36]  = (uint32_t(*)[64][36])(dsm + FS_SX);
    uint32_t (*sW1)[40]     = (uint32_t(*)[40])(dsm + FS_W1);
    uint32_t (*sW2)[136]    = (uint32_t(*)[136])(dsm + FS_W2);
    uint32_t (*sH)[136]     = (uint32_t(*)[136])(dsm + FS_H);

    const int tid = threadIdx.x;
    const int lane = tid & 31, wid = tid >> 5;
    const int gq = lane >> 2, tq = lane & 3;
    const int rw = (wid >> 1) * 16;               // warp row base in tile
    const int rr1 = rw + gq, rr2 = rr1 + 8;       // warp's two row groups
    const int cb = (wid & 1) * 64;                // GEMM1 col half
    const int cb2 = (wid & 1) * 32;               // GEMM2 col half
    const int T = gridDim.x;                      // stride over tiles

    // ---- stage weights ONCE ----
    for (int i = tid; i < 512; i += 256) {
        int r = i >> 2, c8 = (i & 3) * 8;
        float4 w0 = *(const float4*)&W1[(size_t)r * D0 + c8];
        float4 w1 = *(const float4*)&W1[(size_t)r * D0 + c8 + 4];
        uint32_t q0[4] = { f2tf(w0.x), f2tf(w0.y), f2tf(w0.z), f2tf(w0.w) };
        uint32_t q1[4] = { f2tf(w1.x), f2tf(w1.y), f2tf(w1.z), f2tf(w1.w) };
#pragma unroll
        for (int t = 0; t < 4; t++)
            *(uint2*)&sW1[r][c8 + 2 * t] = make_uint2(q0[t], q1[t]);
    }
    for (int i = tid; i < 1024; i += 256) {
        int c = i >> 4, c8 = (i & 15) * 8;
        float4 w0 = *(const float4*)&W2[(size_t)c * D1 + c8];
        float4 w1 = *(const float4*)&W2[(size_t)c * D1 + c8 + 4];
        uint32_t q0[4] = { f2tf(w0.x), f2tf(w0.y), f2tf(w0.z), f2tf(w0.w) };
        uint32_t q1[4] = { f2tf(w1.x), f2tf(w1.y), f2tf(w1.z), f2tf(w1.w) };
#pragma unroll
        for (int t = 0; t < 4; t++)
            *(uint2*)&sW2[c][c8 + 2 * t] = make_uint2(q0[t], q1[t]);
    }

    // x tile loader: 256 threads x 2 cp.async(16B) = 64 rows x 128B
    const int lrow = tid >> 2, lc16 = (tid & 3) * 2;   // chunk pair per thread

#define FUS_ISSUE(TIDX, BUF) do {                                             \
        long long _R0 = (long long)(TIDX) * FROWS;                            \
        _Pragma("unroll")                                                     \
        for (int _i = 0; _i < 2; _i++) {                                      \
            long long _r = _R0 + lrow;                                        \
            int _sz = (_r < N) ? 16 : 0;                                      \
            const float* _src = x + (size_t)min(_r, (long long)N - 1) * D0    \
                                  + (lc16 + _i) * 4;                          \
            uint32_t _dst = (uint32_t)__cvta_generic_to_shared(               \
                &sX[BUF][lrow][(lc16 + _i) * 4]);                             \
            asm volatile("cp.async.ca.shared.global [%0], [%1], 16, %2;"      \
                         :: "r"(_dst), "l"(_src), "r"(_sz) : "memory");       \
        }                                                                     \
    } while (0)

    int tidx = blockIdx.x;
    if (tidx < nblk) FUS_ISSUE(tidx, 0);
    asm volatile("cp.async.commit_group;" ::: "memory");

    for (int k = 0; tidx < nblk; k++, tidx += T) {
        const long long R0 = (long long)tidx * FROWS;
        const int nrows = (int)min((long long)FROWS, (long long)N - R0);

        asm volatile("cp.async.wait_group 0;" ::: "memory");
        __syncthreads();   // x tile ready; everyone done with prior iteration

        // prefetch next tile while computing this one
        int ntidx = tidx + T;
        if (ntidx < nblk) FUS_ISSUE(ntidx, (k + 1) & 1);
        asm volatile("cp.async.commit_group;" ::: "memory");

        // early meta loads (L2-cached)
        const int mr1 = min(rr1, nrows - 1), mr2 = min(rr2, nrows - 1);
        const int gA = g_ni[R0 + mr1], gB = g_ni[R0 + mr2];
        const int p1 = g_pos[R0 + mr1], p2 = g_pos[R0 + mr2];
        const int g0 = g_ni[R0];
        const bool uniform = (g_ni[R0 + nrows - 1] == g0);

        const uint32_t (*cx)[36] = sX[k & 1];

        // ---- GEMM1: warp tile 16 rows x 64 cols, K=32 ----
        float acc[8][4];
#pragma unroll
        for (int nf = 0; nf < 8; nf++)
#pragma unroll
            for (int q = 0; q < 4; q++) acc[nf][q] = 0.f;

#pragma unroll
        for (int ks = 0; ks < 4; ks++) {
            const int k0 = ks * 8 + tq;
            uint32_t a[4];
            a[0] = cx[rr1][k0];     a[1] = cx[rr2][k0];
            a[2] = cx[rr1][k0 + 4]; a[3] = cx[rr2][k0 + 4];
            const int kp = ks * 8 + 2 * tq;
#pragma unroll
            for (int nf = 0; nf < 8; nf++) {
                const int cn = cb + nf * 8 + gq;
                uint2 bb = *(const uint2*)&sW1[cn][kp];
                uint32_t b[2] = { bb.x, bb.y };
                mma_tf32(acc[nf], a, b);
            }
        }

        // ---- normalize + leaky -> sH (perm cols) ----
        if (uniform) {
            const float* scp = &g_scale1[g0 * D1];
            const float* shp = &g_shift1[g0 * D1];
#pragma unroll
            for (int nf = 0; nf < 8; nf++)
#pragma unroll
                for (int j = 0; j < 2; j++) {
                    int c = cb + nf * 8 + 2 * tq + j;
                    float sc = __ldg(&scp[c]);
                    float sh = __ldg(&b1[c]) * sc + __ldg(&shp[c]);
                    float t1 = acc[nf][j] * sc + sh;
                    float t2 = acc[nf][j + 2] * sc + sh;
                    int cp = kperm(c);
                    sH[rr1][cp] = f2tf(fmaxf(t1, SLOPE * t1));
                    sH[rr2][cp] = f2tf(fmaxf(t2, SLOPE * t2));
                }
        } else {
#pragma unroll
            for (int nf = 0; nf < 8; nf++)
#pragma unroll
                for (int j = 0; j < 2; j++) {
                    int c = cb + nf * 8 + 2 * tq + j;
                    float bias = __ldg(&b1[c]);
                    float s1v = g_scale1[gA * D1 + c], h1v = g_shift1[gA * D1 + c];
                    float s2v = g_scale1[gB * D1 + c], h2v = g_shift1[gB * D1 + c];
                    float t1 = (acc[nf][j] + bias) * s1v + h1v;
                    float t2 = (acc[nf][j + 2] + bias) * s2v + h2v;
                    int cp = kperm(c);
                    sH[rr1][cp] = f2tf(fmaxf(t1, SLOPE * t1));
                    sH[rr2][cp] = f2tf(fmaxf(t2, SLOPE * t2));
                }
        }
        __syncthreads();   // sH complete across warps

        // ---- GEMM2: warp tile 16 rows x 32 cols, K=128 ----
        float acc2[4][4];
#pragma unroll
        for (int nf = 0; nf < 4; nf++)
#pragma unroll
            for (int q = 0; q < 4; q++) acc2[nf][q] = 0.f;

#pragma unroll
        for (int kg = 0; kg < 16; kg++) {
            const int kp = kg * 8 + 2 * tq;
            uint2 pa = *(const uint2*)&sH[rr1][kp];
            uint2 pb = *(const uint2*)&sH[rr2][kp];
            uint32_t a[4] = { pa.x, pb.x, pa.y, pb.y };
#pragma unroll
            for (int nf = 0; nf < 4; nf++) {
                const int cn = cb2 + nf * 8 + gq;
                uint2 bb = *(const uint2*)&sW2[cn][kp];
                uint32_t b[2] = { bb.x, bb.y };
                mma_tf32(acc2[nf], a, b);
            }
        }

        // ---- epilogue: bias, stats2 (direct global atomics), scatter h2 ----
#pragma unroll
        for (int nf = 0; nf < 4; nf++) {
            int cpair = cb2 + nf * 8 + 2 * tq;
            float bias0 = __ldg(&b2[cpair]);
            float bias1 = __ldg(&b2[cpair + 1]);
            float h0a = acc2[nf][0] + bias0, h1a = acc2[nf][1] + bias1;   // rr1
            float h0b = acc2[nf][2] + bias0, h1b = acc2[nf][3] + bias1;   // rr2
            if (rr1 < nrows) *(float2*)&g_h2[(size_t)p1 * D2 + cpair] = make_float2(h0a, h1a);
            if (rr2 < nrows) *(float2*)&g_h2[(size_t)p2 * D2 + cpair] = make_float2(h0b, h1b);
            if (uniform) {
                float s0 = 0.f, ss0 = 0.f, s1 = 0.f, ss1 = 0.f;
                if (rr1 < nrows) { s0 += h0a; ss0 += h0a * h0a; s1 += h1a; ss1 += h1a * h1a; }
                if (rr2 < nrows) { s0 += h0b; ss0 += h0b * h0b; s1 += h1b; ss1 += h1b * h1b; }
#pragma unroll
                for (int off = 4; off < 32; off <<= 1) {
                    s0  += __shfl_xor_sync(0xffffffffu, s0, off);
                    ss0 += __shfl_xor_sync(0xffffffffu, ss0, off);
                    s1  += __shfl_xor_sync(0xffffffffu, s1, off);
                    ss1 += __shfl_xor_sync(0xffffffffu, ss1, off);
                }
                if (lane < 4) {
                    atomicAdd(&g_acc[OFF_S2 + g0 * D2 + cpair], s0);
                    atomicAdd(&g_acc[OFF_S2 + g0 * D2 + cpair + 1], s1);
                    atomicAdd(&g_acc[OFF_SS2 + g0 * D2 + cpair], ss0);
                    atomicAdd(&g_acc[OFF_SS2 + g0 * D2 + cpair + 1], ss1);
                }
            } else {
                if (rr1 < nrows) {
                    atomicAdd(&g_acc[OFF_S2 + gA * D2 + cpair], h0a);
                    atomicAdd(&g_acc[OFF_SS2 + gA * D2 + cpair], h0a * h0a);
                    atomicAdd(&g_acc[OFF_S2 + gA * D2 + cpair + 1], h1a);
                    atomicAdd(&g_acc[OFF_SS2 + gA * D2 + cpair + 1], h1a * h1a);
                }
                if (rr2 < nrows) {
                    atomicAdd(&g_acc[OFF_S2 + gB * D2 + cpair], h0b);
                    atomicAdd(&g_acc[OFF_SS2 + gB * D2 + cpair], h0b * h0b);
                    atomicAdd(&g_acc[OFF_S2 + gB * D2 + cpair + 1], h1b);
                    atomicAdd(&g_acc[OFF_SS2 + gB * D2 + cpair + 1], h1b * h1b);
                }
            }
        }
    }
#undef FUS_ISSUE
}

// ---------------------------------------------------------------------------
// Streaming gather-max: h2 rows are already in CSR order -> sequential reads.
__global__ void k_pool(float* __restrict__ out, int M) {
    int w = (blockIdx.x * blockDim.x + threadIdx.x) >> 5;
    int lane = threadIdx.x & 31;
    if (w >= M) return;
    int s = g_segoff[w], e = g_segoff[w + 1];
    float m0 = -3.402823466e38f, m1 = -3.402823466e38f;
    int g = (s < e) ? g_nip[s] : 0;
#pragma unroll 4
    for (int j = s; j < e; ++j) {
        int gn = (j + 1 < e) ? g_nip[j + 1] : 0;
        size_t base = (size_t)j * D2;
        float v0 = g_h2[base + lane];
        float v1 = g_h2[base + 32 + lane];
        float a0 = v0 * g_scale2[g * D2 + lane] + g_shift2[g * D2 + lane];
        float a1 = v1 * g_scale2[g * D2 + 32 + lane] + g_shift2[g * D2 + 32 + lane];
        a0 = fmaxf(a0, SLOPE * a0);
        a1 = fmaxf(a1, SLOPE * a1);
        m0 = fmaxf(m0, a0);
        m1 = fmaxf(m1, a1);
        g = gn;
    }
    if (s == e) { m0 = 0.f; m1 = 0.f; }
    out[(size_t)w * D2 + lane] = m0;
    out[(size_t)w * D2 + 32 + lane] = m1;
}

// ---------------------------------------------------------------------------
extern "C" void kernel_launch(void* const* d_in, const int* in_sizes, int n_in,
                              void* d_out, int out_size) {
    const float* x     = (const float*)d_in[0];
    const float* W1    = (const float*)d_in[1];
    const float* b1    = (const float*)d_in[2];
    const float* g1    = (const float*)d_in[3];
    const float* beta1 = (const float*)d_in[4];
    const float* W2    = (const float*)d_in[5];
    const float* b2    = (const float*)d_in[6];
    const float* g2    = (const float*)d_in[7];
    const float* beta2 = (const float*)d_in[8];
    const void*  nidx  = d_in[9];
    const void*  sidx  = d_in[10];
    float* out = (float*)d_out;

    int N = in_sizes[0] / D0;
    int M = out_size / D2;

    int zgrid = (max(M, GG * 1024) + 255) / 256;
    int ngrid = (N + 255) / 256;
    int nblk = (N + FROWS - 1) / FROWS;
    int pgrid = min(2 * 148, nblk);
    dim3 xgrid((N + XTX_ROWS - 1) / XTX_ROWS, GG);

    cudaFuncSetAttribute(k_fused, cudaFuncAttributeMaxDynamicSharedMemorySize, FUSED_SMEM);
    cudaFuncSetAttribute(k_xtx, cudaFuncAttributeMaxDynamicSharedMemorySize, XTX_SMEM);

    k_zero<<<zgrid, 256>>>(sidx, M);
    k_cvthist<<<ngrid, 256>>>(nidx, sidx, N);
    k_goff<<<1, 32>>>(N);
    k_xtx<<<xgrid, 256, XTX_SMEM>>>(x, N);
    k_scan<<<1, 1024>>>(M);
    k_fill<<<ngrid, 256>>>(N);
    k_fin1<<<GG, 128>>>(W1, b1, g1, beta1, N);
    k_fused<<<pgrid, 256, FUSED_SMEM>>>(x, W1, b1, W2, b2, N, nblk);
    k_fin2<<<GG, 64>>>(g2, beta2, N);
    k_pool<<<(M + 7) / 8, 256>>>(out, M);
}

// round 16
// speedup vs baseline: 1.1663x; 1.1663x over previous
#include <cuda_runtime.h>
#include <cuda_fp16.h>
#include <cstdint>

// ---------------------------------------------------------------------------
// NodeMLP: x[N,32] -> Linear(32,128) -> graphBN(G=16) -> LeakyReLU(0.01)
//          -> Linear(128,64) -> graphBN -> LeakyReLU -> segment_max into M
//
// R16 = R11 (best, 531us) + h2 stored as fp16 (halves fused-write + pool-read
//       traffic; stats still computed in fp32) + XTX_ROWS 1024 (wave packing).
// ---------------------------------------------------------------------------

constexpr int D0 = 32, D1 = 128, D2 = 64, GG = 16;
constexpr float EPS = 1e-5f;
constexpr float SLOPE = 0.01f;

constexpr size_t N_MAX = 1048576;
constexpr size_t M_MAX = 65536;

// layer-2 stats accumulators: [0,1024) sum, [1024,2048) sumsq  ([g][64])
constexpr int OFF_S2 = 0, OFF_SS2 = 1024, ACC_TOT = 2048;

__device__ __half g_h2[N_MAX * (size_t)D2]; // raw h2 (fp16), CSR-permuted rows
__device__ float g_acc[ACC_TOT];
__device__ float g_S[GG * 1024];             // per-graph x^T x (32x32)
__device__ float g_m[GG * 32];               // per-graph sum x
__device__ float g_scale1[GG * D1], g_shift1[GG * D1];
__device__ float g_scale2[GG * D2], g_shift2[GG * D2];
__device__ int   g_ni[N_MAX], g_si[N_MAX];
__device__ int   g_pos[N_MAX];               // node -> CSR slot
__device__ int   g_nip[N_MAX];               // CSR slot -> graph id
__device__ int   g_segcnt[M_MAX], g_segoff[M_MAX + 1], g_cursor[M_MAX];
__device__ int   g_goff[GG + 1];
__device__ int   g_is64;

// ---------------------------------------------------------------------------
__device__ __forceinline__ uint32_t f2tf(float f) {
    uint32_t u;
    asm("cvt.rna.tf32.f32 %0, %1;" : "=r"(u) : "f"(f));
    return u;
}

// D += A(16x8,row) * B(8x8,col)   tf32 in, fp32 accum
__device__ __forceinline__ void mma_tf32(float* d, const uint32_t* a, const uint32_t* b) {
    asm volatile(
        "mma.sync.aligned.m16n8k8.row.col.f32.tf32.tf32.f32 "
        "{%0,%1,%2,%3}, {%4,%5,%6,%7}, {%8,%9}, {%0,%1,%2,%3};"
        : "+f"(d[0]), "+f"(d[1]), "+f"(d[2]), "+f"(d[3])
        : "r"(a[0]), "r"(a[1]), "r"(a[2]), "r"(a[3]), "r"(b[0]), "r"(b[1]));
}

// permuted position of k within its 8-group: (k,k+4) become adjacent
__device__ __forceinline__ int kperm(int k) {
    return (k & ~7) | ((k & 3) << 1) | ((k >> 2) & 1);
}

// first index i in sorted g_ni[0..n) with g_ni[i] >= v
__device__ __forceinline__ int lbound(int n, int v) {
    int lo = 0, hi = n;
    while (lo < hi) {
        int mid = (lo + hi) >> 1;
        if (g_ni[mid] < v) lo = mid + 1; else hi = mid;
    }
    return lo;
}

// ---------------------------------------------------------------------------
// zero + detect (int64 vs int32 index width) merged
__global__ void k_zero(const void* sidx, int M) {
    int i = blockIdx.x * blockDim.x + threadIdx.x;
    if (i == 0) {
        const long long* p = (const long long*)sidx;
        int ok64 = 1;
        for (int t = 0; t < 256; t++) {
            unsigned long long v = (unsigned long long)p[t];
            if (v >= (unsigned long long)M) { ok64 = 0; break; }
        }
        g_is64 = ok64;
    }
    if (i < ACC_TOT) g_acc[i] = 0.f;
    if (i < GG * 1024) g_S[i] = 0.f;
    if (i < GG * 32) g_m[i] = 0.f;
    if (i < M) { g_segcnt[i] = 0; g_cursor[i] = 0; }
}

// convert indices to int32 + histogram super_index in one pass
__global__ void k_cvthist(const void* nidx, const void* sidx, int N) {
    int i = blockIdx.x * blockDim.x + threadIdx.x;
    if (i >= N) return;
    int ni, si;
    if (g_is64) {
        ni = (int)((const long long*)nidx)[i];
        si = (int)((const long long*)sidx)[i];
    } else {
        ni = ((const int*)nidx)[i];
        si = ((const int*)sidx)[i];
    }
    g_ni[i] = ni;
    g_si[i] = si;
    atomicAdd(&g_segcnt[si], 1);
}

// per-graph row ranges (norm_index is sorted)
__global__ void k_goff(int N) {
    int t = threadIdx.x;
    if (t <= GG) g_goff[t] = lbound(N, t);
}

// ---------------------------------------------------------------------------
// Per-graph moments via tf32 MMA with a 4-stage cp.async pipeline.
// A channel of constant 1.0 is appended (col 32) so S[i][32] = m[i].
constexpr int XTX_ROWS   = 1024;                       // rows per block
constexpr int XTX_STAGES = 4;
constexpr int XTX_STG_B  = 128 * 40 * 4;               // one stage: 128 rows x 40 cols
constexpr int XTX_SMEM   = XTX_STAGES * XTX_STG_B + 32 * 33 * 4;

__global__ __launch_bounds__(256) void k_xtx(const float* __restrict__ x, int N) {
    extern __shared__ unsigned char xsm[];
    uint32_t (*sX)[128][40] = (uint32_t(*)[128][40])xsm;
    float* sS = (float*)(xsm + XTX_STAGES * XTX_STG_B);   // [32][33]

    const int g = blockIdx.y;
    const int lo = g_goff[g], hi = g_goff[g + 1];
    const long long base = (long long)lo + (long long)blockIdx.x * XTX_ROWS;
    if (base >= hi) return;
    const int rows = min(XTX_ROWS, (int)(hi - base));
    const int nchunks = (rows + 127) >> 7;

    const int tid = threadIdx.x, lane = tid & 31, wid = tid >> 5;

    for (int i = tid; i < 32 * 33; i += 256) sS[i] = 0.f;
    // ones column (32) + zero pad (33..39), static for all stages
    for (int i = tid; i < XTX_STAGES * 128; i += 256) {
        int s = i >> 7, r = i & 127;
        sX[s][r][32] = 0x3f800000u;
#pragma unroll
        for (int c = 33; c < 40; c++) sX[s][r][c] = 0u;
    }
    __syncthreads();

    const int lrow = tid >> 1, lcol = (tid & 1) * 16;

#define XTX_ISSUE(CH) do {                                                    \
        int _r = (CH) * 128 + lrow;                                           \
        int _sz = (_r < rows) ? 16 : 0;                                       \
        const float* _src = x + (size_t)(base + min(_r, rows - 1)) * D0 + lcol; \
        uint32_t _dst = (uint32_t)__cvta_generic_to_shared(&sX[(CH) & 3][lrow][lcol]); \
        _Pragma("unroll")                                                     \
        for (int _i = 0; _i < 4; _i++)                                        \
            asm volatile("cp.async.ca.shared.global [%0], [%1], 16, %2;"      \
                         :: "r"(_dst + 16 * _i), "l"(_src + 4 * _i), "r"(_sz) \
                         : "memory");                                         \
    } while (0)

    for (int ch = 0; ch < 3; ch++) {
        if (ch < nchunks) XTX_ISSUE(ch);
        asm volatile("cp.async.commit_group;" ::: "memory");
    }

    float acc[2][5][4];
#pragma unroll
    for (int m = 0; m < 2; m++)
#pragma unroll
        for (int jf = 0; jf < 5; jf++)
#pragma unroll
            for (int q = 0; q < 4; q++) acc[m][jf][q] = 0.f;

    for (int ch = 0; ch < nchunks; ch++) {
        asm volatile("cp.async.wait_group 2;" ::: "memory");
        __syncthreads();
        if (ch + 3 < nchunks) XTX_ISSUE(ch + 3);
        asm volatile("cp.async.commit_group;" ::: "memory");

        const uint32_t (*cur)[40] = sX[ch & 3];
#pragma unroll
        for (int half = 0; half < 2; half++) {
            const int k0 = half * 64 + wid * 8 + (lane & 3);
            uint32_t a[2][4];
#pragma unroll
            for (int m = 0; m < 2; m++) {
                int i0 = (lane >> 2) + 16 * m;
                a[m][0] = cur[k0][i0];     a[m][1] = cur[k0][i0 + 8];
                a[m][2] = cur[k0 + 4][i0]; a[m][3] = cur[k0 + 4][i0 + 8];
            }
#pragma unroll
            for (int jf = 0; jf < 5; jf++) {
                int j0 = jf * 8 + (lane >> 2);
                uint32_t b[2] = { cur[k0][j0], cur[k0 + 4][j0] };
#pragma unroll
                for (int m = 0; m < 2; m++) mma_tf32(acc[m][jf], a[m], b);
            }
        }
    }
#undef XTX_ISSUE

#pragma unroll
    for (int m = 0; m < 2; m++)
#pragma unroll
        for (int jf = 0; jf < 5; jf++)
#pragma unroll
            for (int q = 0; q < 4; q++) {
                int i = (lane >> 2) + 16 * m + 8 * (q >> 1);
                int j = jf * 8 + 2 * (lane & 3) + (q & 1);
                if (j <= 32) atomicAdd(&sS[i * 33 + j], acc[m][jf][q]);
            }
    __syncthreads();

    for (int e = tid; e < 32 * 33; e += 256) {
        int i = e / 33, j = e % 33;
        if (j < 32) atomicAdd(&g_S[g * 1024 + i * 32 + j], sS[e]);
        else        atomicAdd(&g_m[g * 32 + i], sS[e]);
    }
}

// ---------------------------------------------------------------------------
// layer-1 scale/shift from analytic moments. grid = GG blocks x 128 threads.
__global__ void k_fin1(const float* __restrict__ W1, const float* __restrict__ b1,
                       const float* __restrict__ gamma, const float* __restrict__ beta,
                       int N)
{
    __shared__ float sS[1024];
    __shared__ float sM[32];
    const int g = blockIdx.x, c = threadIdx.x;
    for (int i = c; i < 1024; i += 128) sS[i] = g_S[g * 1024 + i];
    if (c < 32) sM[c] = g_m[g * 32 + c];
    __syncthreads();

    float w[32];
#pragma unroll
    for (int k = 0; k < 32; k++) w[k] = W1[c * 32 + k];

    float dot = 0.f, quad = 0.f;
#pragma unroll 4
    for (int k = 0; k < 32; k++) {
        float t = 0.f;
#pragma unroll
        for (int l = 0; l < 32; l++) t += sS[k * 32 + l] * w[l];
        quad += w[k] * t;
        dot += w[k] * sM[k];
    }
    float cnt = (float)(g_goff[g + 1] - g_goff[g]);
    float bias = b1[c];
    float sum_h = dot + cnt * bias;
    float sumsq = quad + 2.f * bias * dot + cnt * bias * bias;
    float cc = fmaxf(cnt, 1.f);
    float mean = sum_h / cc;
    float var = fmaxf(sumsq / cc - mean * mean, 0.f);
    float s = gamma[c] * rsqrtf(var + EPS);
    g_scale1[g * D1 + c] = s;
    g_shift1[g * D1 + c] = beta[c] - mean * s;
}

// layer-2 scale/shift from accumulated stats. grid = GG x 64.
__global__ void k_fin2(const float* __restrict__ gamma, const float* __restrict__ beta, int N) {
    const int g = blockIdx.x, c = threadIdx.x;
    float cc = fmaxf((float)(g_goff[g + 1] - g_goff[g]), 1.f);
    float mean = g_acc[OFF_S2 + g * D2 + c] / cc;
    float var = fmaxf(g_acc[OFF_SS2 + g * D2 + c] / cc - mean * mean, 0.f);
    float s = gamma[c] * rsqrtf(var + EPS);
    g_scale2[g * D2 + c] = s;
    g_shift2[g * D2 + c] = beta[c] - mean * s;
}

// fast two-level scan, single block of 1024 threads
__global__ void k_scan(int M) {
    __shared__ int wsum[32];
    int tid = threadIdx.x, lane = tid & 31, w = tid >> 5;
    int per = (M + 1023) >> 10;
    int s = tid * per;
    int e = min(s + per, M);
    int sum = 0;
    for (int i = s; i < e; i++) sum += g_segcnt[i];
    int v = sum;
#pragma unroll
    for (int off = 1; off < 32; off <<= 1) {
        int t = __shfl_up_sync(0xffffffffu, v, off);
        if (lane >= off) v += t;
    }
    if (lane == 31) wsum[w] = v;
    __syncthreads();
    if (w == 0) {
        int t = wsum[lane];
#pragma unroll
        for (int off = 1; off < 32; off <<= 1) {
            int u = __shfl_up_sync(0xffffffffu, t, off);
            if (lane >= off) t += u;
        }
        wsum[lane] = t;
    }
    __syncthreads();
    int run = (w ? wsum[w - 1] : 0) + (v - sum);
    for (int i = s; i < e; i++) { g_segoff[i] = run; run += g_segcnt[i]; }
    if (e == M) g_segoff[M] = run;
}

// CSR slot assignment: node i -> pos; also slot -> graph id for the pool
__global__ void k_fill(int N) {
    int i = blockIdx.x * blockDim.x + threadIdx.x;
    if (i >= N) return;
    int s = g_si[i];
    int pos = g_segoff[s] + atomicAdd(&g_cursor[s], 1);
    g_pos[i] = pos;
    g_nip[pos] = g_ni[i];
}

// ---------------------------------------------------------------------------
// Fused: GEMM1 -> normalize+leaky into sH -> GEMM2 -> stats2 -> scatter h2
// (fp16). 256 threads, 128-row x 128-col tile, 112KB smem -> 2 CTAs/SM.
constexpr int SH_BYTES   = 128 * 136 * 4;     // 69632
constexpr int PH1_BYTES  = 2 * 128 * 40 * 4;  // 40960 (>= sW2: 64*136*4=34816)
constexpr int FUSED_SMEM = SH_BYTES + PH1_BYTES + 512 + 512 + 512;  // 112128

__global__ __launch_bounds__(256, 2) void k_fused(
    const float* __restrict__ x, const float* __restrict__ W1,
    const float* __restrict__ b1, const float* __restrict__ W2,
    const float* __restrict__ b2, int N)
{
    extern __shared__ unsigned char dsm[];
    uint32_t (*sH)[136]  = (uint32_t(*)[136])dsm;
    uint32_t (*sA)[40]   = (uint32_t(*)[40])(dsm + SH_BYTES);
    uint32_t (*sW1)[40]  = (uint32_t(*)[40])(dsm + SH_BYTES + 128 * 40 * 4);
    uint32_t (*sW2)[136] = (uint32_t(*)[136])(dsm + SH_BYTES);
    float* red2 = (float*)(dsm + SH_BYTES + PH1_BYTES);           // [128]
    int*   sg   = (int*)(dsm + SH_BYTES + PH1_BYTES + 512);       // [128]
    int*   spos = (int*)(dsm + SH_BYTES + PH1_BYTES + 1024);      // [128]

    const int tid = threadIdx.x;
    const int r0 = blockIdx.x * 128;
    const int nrows = min(128, N - r0);

    const int lane = tid & 31, wid = tid >> 5;          // 8 warps
    const int rb0 = (wid >> 1) * 32, cb = (wid & 1) * 64;

    // load x -> sA, W1 -> sW1 with perm layout (STS.64 pairs)
    for (int i = tid; i < 512; i += 256) {
        int r = i >> 2, c8 = (i & 3) * 8;
        float4 v0, v1;
        if (r < nrows) {
            v0 = *(const float4*)&x[(size_t)(r0 + r) * D0 + c8];
            v1 = *(const float4*)&x[(size_t)(r0 + r) * D0 + c8 + 4];
        } else { v0 = make_float4(0.f,0.f,0.f,0.f); v1 = v0; }
        uint32_t p0[4] = { f2tf(v0.x), f2tf(v0.y), f2tf(v0.z), f2tf(v0.w) };
        uint32_t pq[4] = { f2tf(v1.x), f2tf(v1.y), f2tf(v1.z), f2tf(v1.w) };
#pragma unroll
        for (int t = 0; t < 4; t++)
            *(uint2*)&sA[r][c8 + 2 * t] = make_uint2(p0[t], pq[t]);

        float4 w0 = *(const float4*)&W1[(size_t)r * D0 + c8];
        float4 w1 = *(const float4*)&W1[(size_t)r * D0 + c8 + 4];
        uint32_t q0[4] = { f2tf(w0.x), f2tf(w0.y), f2tf(w0.z), f2tf(w0.w) };
        uint32_t q1[4] = { f2tf(w1.x), f2tf(w1.y), f2tf(w1.z), f2tf(w1.w) };
#pragma unroll
        for (int t = 0; t < 4; t++)
            *(uint2*)&sW1[r][c8 + 2 * t] = make_uint2(q0[t], q1[t]);
    }
    if (tid < 128) {
        sg[tid] = (tid < nrows) ? g_ni[r0 + tid] : 0;
        spos[tid] = (tid < nrows) ? g_pos[r0 + tid] : 0;
        red2[tid] = 0.f;
    }
    __syncthreads();

    float acc[2][8][4];
#pragma unroll
    for (int mf = 0; mf < 2; mf++)
#pragma unroll
        for (int nf = 0; nf < 8; nf++)
#pragma unroll
            for (int q = 0; q < 4; q++) acc[mf][nf][q] = 0.f;

    // GEMM1 mainloop: LDS.64 frag loads; one b feeds both mf MMAs
#pragma unroll
    for (int ks = 0; ks < 4; ks++) {
        const int kp = ks * 8 + 2 * (lane & 3);
        uint32_t a[2][4];
#pragma unroll
        for (int mf = 0; mf < 2; mf++) {
            int rr1 = rb0 + mf * 16 + (lane >> 2);
            uint2 pa = *(const uint2*)&sA[rr1][kp];
            uint2 pb = *(const uint2*)&sA[rr1 + 8][kp];
            a[mf][0] = pa.x; a[mf][1] = pb.x; a[mf][2] = pa.y; a[mf][3] = pb.y;
        }
#pragma unroll
        for (int nf = 0; nf < 8; nf++) {
            const int cn = cb + nf * 8 + (lane >> 2);
            uint2 bb = *(const uint2*)&sW1[cn][kp];
            uint32_t b[2] = { bb.x, bb.y };
#pragma unroll
            for (int mf = 0; mf < 2; mf++) mma_tf32(acc[mf][nf], a[mf], b);
        }
    }
    __syncthreads();   // done reading sA/sW1; region becomes sW2

    // stage W2 (overlaps normalize below across the co-resident CTA)
    for (int i = tid; i < 1024; i += 256) {
        int c = i >> 4, c8 = (i & 15) * 8;
        float4 w0 = *(const float4*)&W2[(size_t)c * D1 + c8];
        float4 w1 = *(const float4*)&W2[(size_t)c * D1 + c8 + 4];
        uint32_t q0[4] = { f2tf(w0.x), f2tf(w0.y), f2tf(w0.z), f2tf(w0.w) };
        uint32_t q1[4] = { f2tf(w1.x), f2tf(w1.y), f2tf(w1.z), f2tf(w1.w) };
#pragma unroll
        for (int t = 0; t < 4; t++)
            *(uint2*)&sW2[c][c8 + 2 * t] = make_uint2(q0[t], q1[t]);
    }

    const int g0 = sg[0];
    const bool uniform = (sg[nrows - 1] == g0);

    // normalize + leaky -> sH (perm cols; bias folded into shift)
    if (uniform) {
        const float* scp = &g_scale1[g0 * D1];
        const float* shp = &g_shift1[g0 * D1];
#pragma unroll
        for (int nf = 0; nf < 8; nf++)
#pragma unroll
            for (int j = 0; j < 2; j++) {
                int c = cb + nf * 8 + 2 * (lane & 3) + j;
                float sc = __ldg(&scp[c]);
                float sh = __ldg(&b1[c]) * sc + __ldg(&shp[c]);
                int cp = kperm(c);
#pragma unroll
                for (int mf = 0; mf < 2; mf++) {
                    int rr1 = rb0 + mf * 16 + (lane >> 2);
                    float t1 = acc[mf][nf][j] * sc + sh;
                    float t2 = acc[mf][nf][j + 2] * sc + sh;
                    sH[rr1][cp] = f2tf(fmaxf(t1, SLOPE * t1));
                    sH[rr1 + 8][cp] = f2tf(fmaxf(t2, SLOPE * t2));
                }
            }
    } else {
#pragma unroll
        for (int nf = 0; nf < 8; nf++)
#pragma unroll
            for (int j = 0; j < 2; j++) {
                int c = cb + nf * 8 + 2 * (lane & 3) + j;
                float bias = __ldg(&b1[c]);
                int cp = kperm(c);
#pragma unroll
                for (int mf = 0; mf < 2; mf++) {
                    int rr1 = rb0 + mf * 16 + (lane >> 2);
                    int gA = sg[rr1], gB = sg[rr1 + 8];
                    float s1v = g_scale1[gA * D1 + c], h1v = g_shift1[gA * D1 + c];
                    float s2v = g_scale1[gB * D1 + c], h2v = g_shift1[gB * D1 + c];
                    float t1 = (acc[mf][nf][j] + bias) * s1v + h1v;
                    float t2 = (acc[mf][nf][j + 2] + bias) * s2v + h2v;
                    sH[rr1][cp] = f2tf(fmaxf(t1, SLOPE * t1));
                    sH[rr1 + 8][cp] = f2tf(fmaxf(t2, SLOPE * t2));
                }
            }
    }
    __syncthreads();

    // GEMM2: warp tile 32 rows x 32 cols, K=128; LDS.64 frag loads
    const int cb2 = (wid & 1) * 32;
    float acc2[2][4][4];
#pragma unroll
    for (int mf = 0; mf < 2; mf++)
#pragma unroll
        for (int nf = 0; nf < 4; nf++)
#pragma unroll
            for (int q = 0; q < 4; q++) acc2[mf][nf][q] = 0.f;

#pragma unroll
    for (int ks = 0; ks < 16; ks++) {
        const int kp = ks * 8 + 2 * (lane & 3);
        uint32_t a[2][4];
#pragma unroll
        for (int mf = 0; mf < 2; mf++) {
            int rr1 = rb0 + mf * 16 + (lane >> 2);
            uint2 pa = *(const uint2*)&sH[rr1][kp];
            uint2 pb = *(const uint2*)&sH[rr1 + 8][kp];
            a[mf][0] = pa.x; a[mf][1] = pb.x; a[mf][2] = pa.y; a[mf][3] = pb.y;
        }
#pragma unroll
        for (int nf = 0; nf < 4; nf++) {
            const int cn = cb2 + nf * 8 + (lane >> 2);
            uint2 bb = *(const uint2*)&sW2[cn][kp];
            uint32_t b[2] = { bb.x, bb.y };
#pragma unroll
            for (int mf = 0; mf < 2; mf++) mma_tf32(acc2[mf][nf], a[mf], b);
        }
    }

    // epilogue: bias, stats2 (fp32), scatter h2 as fp16 to CSR slots
#pragma unroll
    for (int nf = 0; nf < 4; nf++) {
        int cpair = cb2 + nf * 8 + 2 * (lane & 3);
        float bias0 = __ldg(&b2[cpair]);
        float bias1 = __ldg(&b2[cpair + 1]);
        float s0 = 0.f, ss0 = 0.f, s1 = 0.f, ss1 = 0.f;
#pragma unroll
        for (int mf = 0; mf < 2; mf++) {
            int rr1 = rb0 + mf * 16 + (lane >> 2);
#pragma unroll
            for (int rr = 0; rr < 2; rr++) {
                int r = rr1 + rr * 8;
                float h0 = acc2[mf][nf][2 * rr] + bias0;
                float h1 = acc2[mf][nf][2 * rr + 1] + bias1;
                if (r < nrows) {
                    *(__half2*)&g_h2[(size_t)spos[r] * D2 + cpair] =
                        __floats2half2_rn(h0, h1);
                    if (uniform) {
                        s0 += h0; ss0 += h0 * h0; s1 += h1; ss1 += h1 * h1;
                    } else {
                        int g = sg[r];
                        atomicAdd(&g_acc[OFF_S2 + g * D2 + cpair], h0);
                        atomicAdd(&g_acc[OFF_SS2 + g * D2 + cpair], h0 * h0);
                        atomicAdd(&g_acc[OFF_S2 + g * D2 + cpair + 1], h1);
                        atomicAdd(&g_acc[OFF_SS2 + g * D2 + cpair + 1], h1 * h1);
                    }
                }
            }
        }
        if (uniform) {
#pragma unroll
            for (int off = 4; off < 32; off <<= 1) {
                s0  += __shfl_xor_sync(0xffffffffu, s0, off);
                ss0 += __shfl_xor_sync(0xffffffffu, ss0, off);
                s1  += __shfl_xor_sync(0xffffffffu, s1, off);
                ss1 += __shfl_xor_sync(0xffffffffu, ss1, off);
            }
            if (lane < 4) {
                atomicAdd(&red2[cpair], s0);
                atomicAdd(&red2[cpair + 1], s1);
                atomicAdd(&red2[64 + cpair], ss0);
                atomicAdd(&red2[64 + cpair + 1], ss1);
            }
        }
    }

    if (uniform) {
        __syncthreads();
        if (tid < 64) {
            atomicAdd(&g_acc[OFF_S2 + g0 * D2 + tid], red2[tid]);
            atomicAdd(&g_acc[OFF_SS2 + g0 * D2 + tid], red2[64 + tid]);
        }
    }
}

// ---------------------------------------------------------------------------
// Streaming gather-max: h2 (fp16) rows in CSR order; lane owns channel pair
// (2*lane, 2*lane+1) -> one half2 load per row per lane (128B/row coalesced).
__global__ void k_pool(float* __restrict__ out, int M) {
    int w = (blockIdx.x * blockDim.x + threadIdx.x) >> 5;
    int lane = threadIdx.x & 31;
    if (w >= M) return;
    int s = g_segoff[w], e = g_segoff[w + 1];
    const int c0 = 2 * lane;
    float m0 = -3.402823466e38f, m1 = -3.402823466e38f;
    int g = (s < e) ? g_nip[s] : 0;
    for (int j = s; j < e; ++j) {
        int gn = (j + 1 < e) ? g_nip[j + 1] : 0;
        __half2 hv = *(const __half2*)&g_h2[(size_t)j * D2 + c0];
        float v0 = __low2float(hv), v1 = __high2float(hv);
        float a0 = v0 * g_scale2[g * D2 + c0] + g_shift2[g * D2 + c0];
        float a1 = v1 * g_scale2[g * D2 + c0 + 1] + g_shift2[g * D2 + c0 + 1];
        a0 = fmaxf(a0, SLOPE * a0);
        a1 = fmaxf(a1, SLOPE * a1);
        m0 = fmaxf(m0, a0);
        m1 = fmaxf(m1, a1);
        g = gn;
    }
    if (s == e) { m0 = 0.f; m1 = 0.f; }
    *(float2*)&out[(size_t)w * D2 + c0] = make_float2(m0, m1);
}

// ---------------------------------------------------------------------------
extern "C" void kernel_launch(void* const* d_in, const int* in_sizes, int n_in,
                              void* d_out, int out_size) {
    const float* x     = (const float*)d_in[0];
    const float* W1    = (const float*)d_in[1];
    const float* b1    = (const float*)d_in[2];
    const float* g1    = (const float*)d_in[3];
    const float* beta1 = (const float*)d_in[4];
    const float* W2    = (const float*)d_in[5];
    const float* b2    = (const float*)d_in[6];
    const float* g2    = (const float*)d_in[7];
    const float* beta2 = (const float*)d_in[8];
    const void*  nidx  = d_in[9];
    const void*  sidx  = d_in[10];
    float* out = (float*)d_out;

    int N = in_sizes[0] / D0;
    int M = out_size / D2;

    int zgrid = (max(M, GG * 1024) + 255) / 256;
    int ngrid = (N + 255) / 256;
    int tgrid = (N + 127) / 128;
    dim3 xgrid((N + XTX_ROWS - 1) / XTX_ROWS, GG);

    cudaFuncSetAttribute(k_fused, cudaFuncAttributeMaxDynamicSharedMemorySize, FUSED_SMEM);
    cudaFuncSetAttribute(k_xtx, cudaFuncAttributeMaxDynamicSharedMemorySize, XTX_SMEM);

    k_zero<<<zgrid, 256>>>(sidx, M);
    k_cvthist<<<ngrid, 256>>>(nidx, sidx, N);
    k_goff<<<1, 32>>>(N);
    k_xtx<<<xgrid, 256, XTX_SMEM>>>(x, N);
    k_scan<<<1, 1024>>>(M);
    k_fill<<<ngrid, 256>>>(N);
    k_fin1<<<GG, 128>>>(W1, b1, g1, beta1, N);
    k_fused<<<tgrid, 256, FUSED_SMEM>>>(x, W1, b1, W2, b2, N);
    k_fin2<<<GG, 64>>>(g2, beta2, N);
    k_pool<<<(M + 7) / 8, 256>>>(out, M);
}

// round 17
// speedup vs baseline: 1.3194x; 1.1312x over previous
#include <cuda_runtime.h>
#include <cuda_fp16.h>
#include <cstdint>

// ---------------------------------------------------------------------------
// NodeMLP: x[N,32] -> Linear(32,128) -> graphBN(G=16) -> LeakyReLU(0.01)
//          -> Linear(128,64) -> graphBN -> LeakyReLU -> segment_max into M
//
// R17 = R16 + GEMM2 switched to fp16 m16n8k16 (same mantissa as tf32, half
//       the MMAs and half the smem traffic for sH/sW2) + XTX_ROWS back to
//       2048 (R16 profile showed 1024 regressed) + cursor-free CSR fill.
// ---------------------------------------------------------------------------

constexpr int D0 = 32, D1 = 128, D2 = 64, GG = 16;
constexpr float EPS = 1e-5f;
constexpr float SLOPE = 0.01f;

constexpr size_t N_MAX = 1048576;
constexpr size_t M_MAX = 65536;

// layer-2 stats accumulators: [0,1024) sum, [1024,2048) sumsq  ([g][64])
constexpr int OFF_S2 = 0, OFF_SS2 = 1024, ACC_TOT = 2048;

__device__ __half g_h2[N_MAX * (size_t)D2]; // raw h2 (fp16), CSR-permuted rows
__device__ float g_acc[ACC_TOT];
__device__ float g_S[GG * 1024];             // per-graph x^T x (32x32)
__device__ float g_m[GG * 32];               // per-graph sum x
__device__ float g_scale1[GG * D1], g_shift1[GG * D1];
__device__ float g_scale2[GG * D2], g_shift2[GG * D2];
__device__ int   g_ni[N_MAX], g_si[N_MAX];
__device__ int   g_pos[N_MAX];               // cvthist: rank; after fill: CSR slot
__device__ int   g_nip[N_MAX];               // CSR slot -> graph id
__device__ int   g_segcnt[M_MAX], g_segoff[M_MAX + 1];
__device__ int   g_goff[GG + 1];
__device__ int   g_is64;

// ---------------------------------------------------------------------------
__device__ __forceinline__ uint32_t f2tf(float f) {
    uint32_t u;
    asm("cvt.rna.tf32.f32 %0, %1;" : "=r"(u) : "f"(f));
    return u;
}

// D += A(16x8,row) * B(8x8,col)   tf32 in, fp32 accum
__device__ __forceinline__ void mma_tf32(float* d, const uint32_t* a, const uint32_t* b) {
    asm volatile(
        "mma.sync.aligned.m16n8k8.row.col.f32.tf32.tf32.f32 "
        "{%0,%1,%2,%3}, {%4,%5,%6,%7}, {%8,%9}, {%0,%1,%2,%3};"
        : "+f"(d[0]), "+f"(d[1]), "+f"(d[2]), "+f"(d[3])
        : "r"(a[0]), "r"(a[1]), "r"(a[2]), "r"(a[3]), "r"(b[0]), "r"(b[1]));
}

// D += A(16x16,row) * B(16x8,col)   fp16 in, fp32 accum
__device__ __forceinline__ void mma_f16(float* d, const uint32_t* a, const uint32_t* b) {
    asm volatile(
        "mma.sync.aligned.m16n8k16.row.col.f32.f16.f16.f32 "
        "{%0,%1,%2,%3}, {%4,%5,%6,%7}, {%8,%9}, {%0,%1,%2,%3};"
        : "+f"(d[0]), "+f"(d[1]), "+f"(d[2]), "+f"(d[3])
        : "r"(a[0]), "r"(a[1]), "r"(a[2]), "r"(a[3]), "r"(b[0]), "r"(b[1]));
}

// permuted position of k within its 8-group: (k,k+4) become adjacent
__device__ __forceinline__ int kperm(int k) {
    return (k & ~7) | ((k & 3) << 1) | ((k >> 2) & 1);
}

__device__ __forceinline__ uint32_t h2bits(float a, float b) {
    __half2 h = __floats2half2_rn(a, b);
    return *(uint32_t*)&h;
}

// first index i in sorted g_ni[0..n) with g_ni[i] >= v
__device__ __forceinline__ int lbound(int n, int v) {
    int lo = 0, hi = n;
    while (lo < hi) {
        int mid = (lo + hi) >> 1;
        if (g_ni[mid] < v) lo = mid + 1; else hi = mid;
    }
    return lo;
}

// ---------------------------------------------------------------------------
// zero + detect (int64 vs int32 index width) merged
__global__ void k_zero(const void* sidx, int M) {
    int i = blockIdx.x * blockDim.x + threadIdx.x;
    if (i == 0) {
        const long long* p = (const long long*)sidx;
        int ok64 = 1;
        for (int t = 0; t < 256; t++) {
            unsigned long long v = (unsigned long long)p[t];
            if (v >= (unsigned long long)M) { ok64 = 0; break; }
        }
        g_is64 = ok64;
    }
    if (i < ACC_TOT) g_acc[i] = 0.f;
    if (i < GG * 1024) g_S[i] = 0.f;
    if (i < GG * 32) g_m[i] = 0.f;
    if (i < M) g_segcnt[i] = 0;
}

// convert indices to int32 + histogram; histogram return value = rank
__global__ void k_cvthist(const void* nidx, const void* sidx, int N) {
    int i = blockIdx.x * blockDim.x + threadIdx.x;
    if (i >= N) return;
    int ni, si;
    if (g_is64) {
        ni = (int)((const long long*)nidx)[i];
        si = (int)((const long long*)sidx)[i];
    } else {
        ni = ((const int*)nidx)[i];
        si = ((const int*)sidx)[i];
    }
    g_ni[i] = ni;
    g_si[i] = si;
    g_pos[i] = atomicAdd(&g_segcnt[si], 1);   // within-segment rank
}

// per-graph row ranges (norm_index is sorted)
__global__ void k_goff(int N) {
    int t = threadIdx.x;
    if (t <= GG) g_goff[t] = lbound(N, t);
}

// ---------------------------------------------------------------------------
// Per-graph moments via tf32 MMA with a 4-stage cp.async pipeline.
// A channel of constant 1.0 is appended (col 32) so S[i][32] = m[i].
constexpr int XTX_ROWS   = 2048;
constexpr int XTX_STAGES = 4;
constexpr int XTX_STG_B  = 128 * 40 * 4;
constexpr int XTX_SMEM   = XTX_STAGES * XTX_STG_B + 32 * 33 * 4;

__global__ __launch_bounds__(256) void k_xtx(const float* __restrict__ x, int N) {
    extern __shared__ unsigned char xsm[];
    uint32_t (*sX)[128][40] = (uint32_t(*)[128][40])xsm;
    float* sS = (float*)(xsm + XTX_STAGES * XTX_STG_B);   // [32][33]

    const int g = blockIdx.y;
    const int lo = g_goff[g], hi = g_goff[g + 1];
    const long long base = (long long)lo + (long long)blockIdx.x * XTX_ROWS;
    if (base >= hi) return;
    const int rows = min(XTX_ROWS, (int)(hi - base));
    const int nchunks = (rows + 127) >> 7;

    const int tid = threadIdx.x, lane = tid & 31, wid = tid >> 5;

    for (int i = tid; i < 32 * 33; i += 256) sS[i] = 0.f;
    for (int i = tid; i < XTX_STAGES * 128; i += 256) {
        int s = i >> 7, r = i & 127;
        sX[s][r][32] = 0x3f800000u;
#pragma unroll
        for (int c = 33; c < 40; c++) sX[s][r][c] = 0u;
    }
    __syncthreads();

    const int lrow = tid >> 1, lcol = (tid & 1) * 16;

#define XTX_ISSUE(CH) do {                                                    \
        int _r = (CH) * 128 + lrow;                                           \
        int _sz = (_r < rows) ? 16 : 0;                                       \
        const float* _src = x + (size_t)(base + min(_r, rows - 1)) * D0 + lcol; \
        uint32_t _dst = (uint32_t)__cvta_generic_to_shared(&sX[(CH) & 3][lrow][lcol]); \
        _Pragma("unroll")                                                     \
        for (int _i = 0; _i < 4; _i++)                                        \
            asm volatile("cp.async.ca.shared.global [%0], [%1], 16, %2;"      \
                         :: "r"(_dst + 16 * _i), "l"(_src + 4 * _i), "r"(_sz) \
                         : "memory");                                         \
    } while (0)

    for (int ch = 0; ch < 3; ch++) {
        if (ch < nchunks) XTX_ISSUE(ch);
        asm volatile("cp.async.commit_group;" ::: "memory");
    }

    float acc[2][5][4];
#pragma unroll
    for (int m = 0; m < 2; m++)
#pragma unroll
        for (int jf = 0; jf < 5; jf++)
#pragma unroll
            for (int q = 0; q < 4; q++) acc[m][jf][q] = 0.f;

    for (int ch = 0; ch < nchunks; ch++) {
        asm volatile("cp.async.wait_group 2;" ::: "memory");
        __syncthreads();
        if (ch + 3 < nchunks) XTX_ISSUE(ch + 3);
        asm volatile("cp.async.commit_group;" ::: "memory");

        const uint32_t (*cur)[40] = sX[ch & 3];
#pragma unroll
        for (int half = 0; half < 2; half++) {
            const int k0 = half * 64 + wid * 8 + (lane & 3);
            uint32_t a[2][4];
#pragma unroll
            for (int m = 0; m < 2; m++) {
                int i0 = (lane >> 2) + 16 * m;
                a[m][0] = cur[k0][i0];     a[m][1] = cur[k0][i0 + 8];
                a[m][2] = cur[k0 + 4][i0]; a[m][3] = cur[k0 + 4][i0 + 8];
            }
#pragma unroll
            for (int jf = 0; jf < 5; jf++) {
                int j0 = jf * 8 + (lane >> 2);
                uint32_t b[2] = { cur[k0][j0], cur[k0 + 4][j0] };
#pragma unroll
                for (int m = 0; m < 2; m++) mma_tf32(acc[m][jf], a[m], b);
            }
        }
    }
#undef XTX_ISSUE

#pragma unroll
    for (int m = 0; m < 2; m++)
#pragma unroll
        for (int jf = 0; jf < 5; jf++)
#pragma unroll
            for (int q = 0; q < 4; q++) {
                int i = (lane >> 2) + 16 * m + 8 * (q >> 1);
                int j = jf * 8 + 2 * (lane & 3) + (q & 1);
                if (j <= 32) atomicAdd(&sS[i * 33 + j], acc[m][jf][q]);
            }
    __syncthreads();

    for (int e = tid; e < 32 * 33; e += 256) {
        int i = e / 33, j = e % 33;
        if (j < 32) atomicAdd(&g_S[g * 1024 + i * 32 + j], sS[e]);
        else        atomicAdd(&g_m[g * 32 + i], sS[e]);
    }
}

// ---------------------------------------------------------------------------
// layer-1 scale/shift from analytic moments. grid = GG blocks x 128 threads.
__global__ void k_fin1(const float* __restrict__ W1, const float* __restrict__ b1,
                       const float* __restrict__ gamma, const float* __restrict__ beta,
                       int N)
{
    __shared__ float sS[1024];
    __shared__ float sM[32];
    const int g = blockIdx.x, c = threadIdx.x;
    for (int i = c; i < 1024; i += 128) sS[i] = g_S[g * 1024 + i];
    if (c < 32) sM[c] = g_m[g * 32 + c];
    __syncthreads();

    float w[32];
#pragma unroll
    for (int k = 0; k < 32; k++) w[k] = W1[c * 32 + k];

    float dot = 0.f, quad = 0.f;
#pragma unroll 4
    for (int k = 0; k < 32; k++) {
        float t = 0.f;
#pragma unroll
        for (int l = 0; l < 32; l++) t += sS[k * 32 + l] * w[l];
        quad += w[k] * t;
        dot += w[k] * sM[k];
    }
    float cnt = (float)(g_goff[g + 1] - g_goff[g]);
    float bias = b1[c];
    float sum_h = dot + cnt * bias;
    float sumsq = quad + 2.f * bias * dot + cnt * bias * bias;
    float cc = fmaxf(cnt, 1.f);
    float mean = sum_h / cc;
    float var = fmaxf(sumsq / cc - mean * mean, 0.f);
    float s = gamma[c] * rsqrtf(var + EPS);
    g_scale1[g * D1 + c] = s;
    g_shift1[g * D1 + c] = beta[c] - mean * s;
}

// layer-2 scale/shift from accumulated stats. grid = GG x 64.
__global__ void k_fin2(const float* __restrict__ gamma, const float* __restrict__ beta, int N) {
    const int g = blockIdx.x, c = threadIdx.x;
    float cc = fmaxf((float)(g_goff[g + 1] - g_goff[g]), 1.f);
    float mean = g_acc[OFF_S2 + g * D2 + c] / cc;
    float var = fmaxf(g_acc[OFF_SS2 + g * D2 + c] / cc - mean * mean, 0.f);
    float s = gamma[c] * rsqrtf(var + EPS);
    g_scale2[g * D2 + c] = s;
    g_shift2[g * D2 + c] = beta[c] - mean * s;
}

// fast two-level scan, single block of 1024 threads
__global__ void k_scan(int M) {
    __shared__ int wsum[32];
    int tid = threadIdx.x, lane = tid & 31, w = tid >> 5;
    int per = (M + 1023) >> 10;
    int s = tid * per;
    int e = min(s + per, M);
    int sum = 0;
    for (int i = s; i < e; i++) sum += g_segcnt[i];
    int v = sum;
#pragma unroll
    for (int off = 1; off < 32; off <<= 1) {
        int t = __shfl_up_sync(0xffffffffu, v, off);
        if (lane >= off) v += t;
    }
    if (lane == 31) wsum[w] = v;
    __syncthreads();
    if (w == 0) {
        int t = wsum[lane];
#pragma unroll
        for (int off = 1; off < 32; off <<= 1) {
            int u = __shfl_up_sync(0xffffffffu, t, off);
            if (lane >= off) t += u;
        }
        wsum[lane] = t;
    }
    __syncthreads();
    int run = (w ? wsum[w - 1] : 0) + (v - sum);
    for (int i = s; i < e; i++) { g_segoff[i] = run; run += g_segcnt[i]; }
    if (e == M) g_segoff[M] = run;
}

// CSR slot assignment from precomputed ranks (no atomics)
__global__ void k_fill(int N) {
    int i = blockIdx.x * blockDim.x + threadIdx.x;
    if (i >= N) return;
    int pos = g_segoff[g_si[i]] + g_pos[i];
    g_pos[i] = pos;
    g_nip[pos] = g_ni[i];
}

// ---------------------------------------------------------------------------
// Fused: GEMM1 (tf32) -> normalize+leaky into sH (fp16) -> GEMM2 (fp16 mma)
// -> stats2 -> scatter h2 (fp16). 256 threads, 128-row tile, ~79KB smem,
// 2 CTAs/SM.
// smem layout (bytes):
//   [0,      36864)  sH16[128][72]  half2 entries (perm cols)
//   [36864,  77824)  phase1: sA[128][40] + sW1[128][40]; later sW2h[64][72]
//   [77824,  78336)  red2[128]
//   [78336,  78848)  sg[128];  [78848, 79360) spos[128]
constexpr int SH_BYTES   = 128 * 72 * 4;      // 36864
constexpr int PH1_BYTES  = 2 * 128 * 40 * 4;  // 40960 (>= sW2h: 64*72*4=18432)
constexpr int FUSED_SMEM = SH_BYTES + PH1_BYTES + 512 + 512 + 512;  // 79360

__global__ __launch_bounds__(256, 2) void k_fused(
    const float* __restrict__ x, const float* __restrict__ W1,
    const float* __restrict__ b1, const float* __restrict__ W2,
    const float* __restrict__ b2, int N)
{
    extern __shared__ unsigned char dsm[];
    uint32_t (*sH16)[72]  = (uint32_t(*)[72])dsm;              // half2 entries
    uint32_t (*sA)[40]    = (uint32_t(*)[40])(dsm + SH_BYTES);
    uint32_t (*sW1)[40]   = (uint32_t(*)[40])(dsm + SH_BYTES + 128 * 40 * 4);
    uint32_t (*sW2h)[72]  = (uint32_t(*)[72])(dsm + SH_BYTES); // half2 entries
    float* red2 = (float*)(dsm + SH_BYTES + PH1_BYTES);           // [128]
    int*   sg   = (int*)(dsm + SH_BYTES + PH1_BYTES + 512);       // [128]
    int*   spos = (int*)(dsm + SH_BYTES + PH1_BYTES + 1024);      // [128]

    const int tid = threadIdx.x;
    const int r0 = blockIdx.x * 128;
    const int nrows = min(128, N - r0);

    const int lane = tid & 31, wid = tid >> 5;          // 8 warps
    const int gq = lane >> 2, tq = lane & 3;
    const int rb0 = (wid >> 1) * 32, cb = (wid & 1) * 64;

    // load x -> sA, W1 -> sW1 with perm layout (STS.64 pairs)
    for (int i = tid; i < 512; i += 256) {
        int r = i >> 2, c8 = (i & 3) * 8;
        float4 v0, v1;
        if (r < nrows) {
            v0 = *(const float4*)&x[(size_t)(r0 + r) * D0 + c8];
            v1 = *(const float4*)&x[(size_t)(r0 + r) * D0 + c8 + 4];
        } else { v0 = make_float4(0.f,0.f,0.f,0.f); v1 = v0; }
        uint32_t p0[4] = { f2tf(v0.x), f2tf(v0.y), f2tf(v0.z), f2tf(v0.w) };
        uint32_t pq[4] = { f2tf(v1.x), f2tf(v1.y), f2tf(v1.z), f2tf(v1.w) };
#pragma unroll
        for (int t = 0; t < 4; t++)
            *(uint2*)&sA[r][c8 + 2 * t] = make_uint2(p0[t], pq[t]);

        float4 w0 = *(const float4*)&W1[(size_t)r * D0 + c8];
        float4 w1 = *(const float4*)&W1[(size_t)r * D0 + c8 + 4];
        uint32_t q0[4] = { f2tf(w0.x), f2tf(w0.y), f2tf(w0.z), f2tf(w0.w) };
        uint32_t q1[4] = { f2tf(w1.x), f2tf(w1.y), f2tf(w1.z), f2tf(w1.w) };
#pragma unroll
        for (int t = 0; t < 4; t++)
            *(uint2*)&sW1[r][c8 + 2 * t] = make_uint2(q0[t], q1[t]);
    }
    if (tid < 128) {
        sg[tid] = (tid < nrows) ? g_ni[r0 + tid] : 0;
        spos[tid] = (tid < nrows) ? g_pos[r0 + tid] : 0;
        red2[tid] = 0.f;
    }
    __syncthreads();

    float acc[2][8][4];
#pragma unroll
    for (int mf = 0; mf < 2; mf++)
#pragma unroll
        for (int nf = 0; nf < 8; nf++)
#pragma unroll
            for (int q = 0; q < 4; q++) acc[mf][nf][q] = 0.f;

    // GEMM1 mainloop (tf32): LDS.64 frag loads; one b feeds both mf MMAs
#pragma unroll
    for (int ks = 0; ks < 4; ks++) {
        const int kp = ks * 8 + 2 * tq;
        uint32_t a[2][4];
#pragma unroll
        for (int mf = 0; mf < 2; mf++) {
            int rr1 = rb0 + mf * 16 + gq;
            uint2 pa = *(const uint2*)&sA[rr1][kp];
            uint2 pb = *(const uint2*)&sA[rr1 + 8][kp];
            a[mf][0] = pa.x; a[mf][1] = pb.x; a[mf][2] = pa.y; a[mf][3] = pb.y;
        }
#pragma unroll
        for (int nf = 0; nf < 8; nf++) {
            const int cn = cb + nf * 8 + gq;
            uint2 bb = *(const uint2*)&sW1[cn][kp];
            uint32_t b[2] = { bb.x, bb.y };
#pragma unroll
            for (int mf = 0; mf < 2; mf++) mma_tf32(acc[mf][nf], a[mf], b);
        }
    }
    __syncthreads();   // done reading sA/sW1; region becomes sW2h

    // stage W2 -> fp16 half2, perm layout (overlaps normalize below)
    for (int i = tid; i < 512; i += 256) {
        int n = i >> 3, g8 = (i & 7) * 8;      // half2-col group base
        int c16 = g8 * 2;                      // starting float col
        const float* wp = &W2[(size_t)n * D1 + c16];
        float4 w0 = *(const float4*)&wp[0];
        float4 w1 = *(const float4*)&wp[4];
        float4 w2 = *(const float4*)&wp[8];
        float4 w3 = *(const float4*)&wp[12];
        uint32_t h[8] = {
            h2bits(w0.x, w0.y), h2bits(w0.z, w0.w),
            h2bits(w1.x, w1.y), h2bits(w1.z, w1.w),
            h2bits(w2.x, w2.y), h2bits(w2.z, w2.w),
            h2bits(w3.x, w3.y), h2bits(w3.z, w3.w) };
#pragma unroll
        for (int t = 0; t < 4; t++)
            *(uint2*)&sW2h[n][g8 + 2 * t] = make_uint2(h[t], h[t + 4]);
    }

    const int g0 = sg[0];
    const bool uniform = (sg[nrows - 1] == g0);

    // normalize + leaky -> sH16 (half2, perm cols; bias folded into shift)
    if (uniform) {
        const float* scp = &g_scale1[g0 * D1];
        const float* shp = &g_shift1[g0 * D1];
#pragma unroll
        for (int nf = 0; nf < 8; nf++) {
            int c = cb + nf * 8 + 2 * tq;
            float sc0 = __ldg(&scp[c]);
            float sh0 = __ldg(&b1[c]) * sc0 + __ldg(&shp[c]);
            float sc1 = __ldg(&scp[c + 1]);
            float sh1 = __ldg(&b1[c + 1]) * sc1 + __ldg(&shp[c + 1]);
            int qp = kperm(c >> 1);
#pragma unroll
            for (int mf = 0; mf < 2; mf++) {
                int rr1 = rb0 + mf * 16 + gq;
                float t0 = acc[mf][nf][0] * sc0 + sh0;
                float t1 = acc[mf][nf][1] * sc1 + sh1;
                float t2 = acc[mf][nf][2] * sc0 + sh0;
                float t3 = acc[mf][nf][3] * sc1 + sh1;
                sH16[rr1][qp]     = h2bits(fmaxf(t0, SLOPE * t0), fmaxf(t1, SLOPE * t1));
                sH16[rr1 + 8][qp] = h2bits(fmaxf(t2, SLOPE * t2), fmaxf(t3, SLOPE * t3));
            }
        }
    } else {
#pragma unroll
        for (int nf = 0; nf < 8; nf++) {
            int c = cb + nf * 8 + 2 * tq;
            float bias0 = __ldg(&b1[c]), bias1 = __ldg(&b1[c + 1]);
            int qp = kperm(c >> 1);
#pragma unroll
            for (int mf = 0; mf < 2; mf++) {
                int rr1 = rb0 + mf * 16 + gq;
                int gA = sg[rr1], gB = sg[rr1 + 8];
                float t0 = (acc[mf][nf][0] + bias0) * g_scale1[gA * D1 + c] + g_shift1[gA * D1 + c];
                float t1 = (acc[mf][nf][1] + bias1) * g_scale1[gA * D1 + c + 1] + g_shift1[gA * D1 + c + 1];
                float t2 = (acc[mf][nf][2] + bias0) * g_scale1[gB * D1 + c] + g_shift1[gB * D1 + c];
                float t3 = (acc[mf][nf][3] + bias1) * g_scale1[gB * D1 + c + 1] + g_shift1[gB * D1 + c + 1];
                sH16[rr1][qp]     = h2bits(fmaxf(t0, SLOPE * t0), fmaxf(t1, SLOPE * t1));
                sH16[rr1 + 8][qp] = h2bits(fmaxf(t2, SLOPE * t2), fmaxf(t3, SLOPE * t3));
            }
        }
    }
    __syncthreads();

    // GEMM2 (fp16 m16n8k16): warp tile 32 rows x 32 cols, 8 k-steps of 16
    const int cb2 = (wid & 1) * 32;
    float acc2[2][4][4];
#pragma unroll
    for (int mf = 0; mf < 2; mf++)
#pragma unroll
        for (int nf = 0; nf < 4; nf++)
#pragma unroll
            for (int q = 0; q < 4; q++) acc2[mf][nf][q] = 0.f;

#pragma unroll
    for (int kg = 0; kg < 8; kg++) {
        const int kp = kg * 8 + 2 * tq;
        uint32_t a[2][4];
#pragma unroll
        for (int mf = 0; mf < 2; mf++) {
            int rr1 = rb0 + mf * 16 + gq;
            uint2 pa = *(const uint2*)&sH16[rr1][kp];       // a0, a2
            uint2 pb = *(const uint2*)&sH16[rr1 + 8][kp];   // a1, a3
            a[mf][0] = pa.x; a[mf][1] = pb.x; a[mf][2] = pa.y; a[mf][3] = pb.y;
        }
#pragma unroll
        for (int nf = 0; nf < 4; nf++) {
            const int cn = cb2 + nf * 8 + gq;
            uint2 bb = *(const uint2*)&sW2h[cn][kp];        // b0, b1
            uint32_t b[2] = { bb.x, bb.y };
#pragma unroll
            for (int mf = 0; mf < 2; mf++) mma_f16(acc2[mf][nf], a[mf], b);
        }
    }

    // epilogue: bias, stats2 (fp32), scatter h2 as fp16 to CSR slots
#pragma unroll
    for (int nf = 0; nf < 4; nf++) {
        int cpair = cb2 + nf * 8 + 2 * tq;
        float bias0 = __ldg(&b2[cpair]);
        float bias1 = __ldg(&b2[cpair + 1]);
        float s0 = 0.f, ss0 = 0.f, s1 = 0.f, ss1 = 0.f;
#pragma unroll
        for (int mf = 0; mf < 2; mf++) {
            int rr1 = rb0 + mf * 16 + gq;
#pragma unroll
            for (int rr = 0; rr < 2; rr++) {
                int r = rr1 + rr * 8;
                float h0 = acc2[mf][nf][2 * rr] + bias0;
                float h1 = acc2[mf][nf][2 * rr + 1] + bias1;
                if (r < nrows) {
                    *(__half2*)&g_h2[(size_t)spos[r] * D2 + cpair] =
                        __floats2half2_rn(h0, h1);
                    if (uniform) {
                        s0 += h0; ss0 += h0 * h0; s1 += h1; ss1 += h1 * h1;
                    } else {
                        int g = sg[r];
                        atomicAdd(&g_acc[OFF_S2 + g * D2 + cpair], h0);
                        atomicAdd(&g_acc[OFF_SS2 + g * D2 + cpair], h0 * h0);
                        atomicAdd(&g_acc[OFF_S2 + g * D2 + cpair + 1], h1);
                        atomicAdd(&g_acc[OFF_SS2 + g * D2 + cpair + 1], h1 * h1);
                    }
                }
            }
        }
        if (uniform) {
#pragma unroll
            for (int off = 4; off < 32; off <<= 1) {
                s0  += __shfl_xor_sync(0xffffffffu, s0, off);
                ss0 += __shfl_xor_sync(0xffffffffu, ss0, off);
                s1  += __shfl_xor_sync(0xffffffffu, s1, off);
                ss1 += __shfl_xor_sync(0xffffffffu, ss1, off);
            }
            if (lane < 4) {
                atomicAdd(&red2[cpair], s0);
                atomicAdd(&red2[cpair + 1], s1);
                atomicAdd(&red2[64 + cpair], ss0);
                atomicAdd(&red2[64 + cpair + 1], ss1);
            }
        }
    }

    if (uniform) {
        __syncthreads();
        if (tid < 64) {
            atomicAdd(&g_acc[OFF_S2 + g0 * D2 + tid], red2[tid]);
            atomicAdd(&g_acc[OFF_SS2 + g0 * D2 + tid], red2[64 + tid]);
        }
    }
}

// ---------------------------------------------------------------------------
// Streaming gather-max: h2 (fp16) rows in CSR order; lane owns channel pair
// (2*lane, 2*lane+1) -> one half2 load per row per lane (128B/row coalesced).
__global__ void k_pool(float* __restrict__ out, int M) {
    int w = (blockIdx.x * blockDim.x + threadIdx.x) >> 5;
    int lane = threadIdx.x & 31;
    if (w >= M) return;
    int s = g_segoff[w], e = g_segoff[w + 1];
    const int c0 = 2 * lane;
    float m0 = -3.402823466e38f, m1 = -3.402823466e38f;
    int g = (s < e) ? g_nip[s] : 0;
    for (int j = s; j < e; ++j) {
        int gn = (j + 1 < e) ? g_nip[j + 1] : 0;
        __half2 hv = *(const __half2*)&g_h2[(size_t)j * D2 + c0];
        float v0 = __low2float(hv), v1 = __high2float(hv);
        float a0 = v0 * g_scale2[g * D2 + c0] + g_shift2[g * D2 + c0];
        float a1 = v1 * g_scale2[g * D2 + c0 + 1] + g_shift2[g * D2 + c0 + 1];
        a0 = fmaxf(a0, SLOPE * a0);
        a1 = fmaxf(a1, SLOPE * a1);
        m0 = fmaxf(m0, a0);
        m1 = fmaxf(m1, a1);
        g = gn;
    }
    if (s == e) { m0 = 0.f; m1 = 0.f; }
    *(float2*)&out[(size_t)w * D2 + c0] = make_float2(m0, m1);
}

// ---------------------------------------------------------------------------
extern "C" void kernel_launch(void* const* d_in, const int* in_sizes, int n_in,
                              void* d_out, int out_size) {
    const float* x     = (const float*)d_in[0];
    const float* W1    = (const float*)d_in[1];
    const float* b1    = (const float*)d_in[2];
    const float* g1    = (const float*)d_in[3];
    const float* beta1 = (const float*)d_in[4];
    const float* W2    = (const float*)d_in[5];
    const float* b2    = (const float*)d_in[6];
    const float* g2    = (const float*)d_in[7];
    const float* beta2 = (const float*)d_in[8];
    const void*  nidx  = d_in[9];
    const void*  sidx  = d_in[10];
    float* out = (float*)d_out;

    int N = in_sizes[0] / D0;
    int M = out_size / D2;

    int zgrid = (max(M, GG * 1024) + 255) / 256;
    int ngrid = (N + 255) / 256;
    int tgrid = (N + 127) / 128;
    dim3 xgrid((N + XTX_ROWS - 1) / XTX_ROWS, GG);

    cudaFuncSetAttribute(k_fused, cudaFuncAttributeMaxDynamicSharedMemorySize, FUSED_SMEM);
    cudaFuncSetAttribute(k_xtx, cudaFuncAttributeMaxDynamicSharedMemorySize, XTX_SMEM);

    k_zero<<<zgrid, 256>>>(sidx, M);
    k_cvthist<<<ngrid, 256>>>(nidx, sidx, N);
    k_goff<<<1, 32>>>(N);
    k_xtx<<<xgrid, 256, XTX_SMEM>>>(x, N);
    k_scan<<<1, 1024>>>(M);
    k_fill<<<ngrid, 256>>>(N);
    k_fin1<<<GG, 128>>>(W1, b1, g1, beta1, N);
    k_fused<<<tgrid, 256, FUSED_SMEM>>>(x, W1, b1, W2, b2, N);
    k_fin2<<<GG, 64>>>(g2, beta2, N);
    k_pool<<<(M + 7) / 8, 256>>>(out, M);
}